// round 2
// baseline (speedup 1.0000x reference)
#include <cuda_runtime.h>
#include <cstdint>
#include <cstddef>

#define BATCH 4096
#define T_SEQ 512
#define SDIM  16
#define ODIM  8
#define IDIM  4
#define RS    32
#define CH    32
#define LCH   16
#define NB    2
#define TPB   128

__device__ float g_M [RS*SDIM*SDIM];
__device__ float g_Kg[RS*SDIM*ODIM];
__device__ float g_Ng[RS*SDIM*IDIM];
__device__ float g_Phi[3*SDIM*SDIM];
__device__ float g_d [(size_t)CH*BATCH*SDIM];
__device__ float g_xs[(size_t)CH*BATCH*SDIM];

__device__ __forceinline__ float det3v(float a00,float a01,float a02,
                                       float a10,float a11,float a12,
                                       float a20,float a21,float a22){
  return a00*(a11*a22-a12*a21)-a01*(a10*a22-a12*a20)+a02*(a10*a21-a11*a20);
}
__device__ __forceinline__ float minor3(const float* M,int ld,int r,int c){
  int rs[3],cs[3]; int q=0;
  for(int a=0;a<4;a++) if(a!=r) rs[q++]=a;
  q=0;
  for(int a=0;a<4;a++) if(a!=c) cs[q++]=a;
  return det3v(M[rs[0]*ld+cs[0]],M[rs[0]*ld+cs[1]],M[rs[0]*ld+cs[2]],
               M[rs[1]*ld+cs[0]],M[rs[1]*ld+cs[1]],M[rs[1]*ld+cs[2]],
               M[rs[2]*ld+cs[0]],M[rs[2]*ld+cs[1]],M[rs[2]*ld+cs[2]]);
}
__device__ __forceinline__ void inv4(const float* M,int ld,float* inv,int t){
  if (t<16){
    int i=t>>2, j=t&3;
    float det=0.f;
    for(int r=0;r<4;r++){
      float sgn=(r&1)?-1.f:1.f;
      det += sgn*M[r*ld]*minor3(M,ld,r,0);
    }
    float cof=(((i+j)&1)?-1.f:1.f)*minor3(M,ld,j,i);
    inv[i*4+j]=cof/det;
  }
}

// K1: Riccati recursion (batch-independent) + chunk propagators. 1 block, 256 thr.
__global__ void riccati_kernel(const float* __restrict__ A_, const float* __restrict__ B_,
                               const float* __restrict__ C_, const float* __restrict__ Q_,
                               const float* __restrict__ R_)
{
  __shared__ float sA[256], sQ[256], sC[128], sB[64], sR[64], sCA[128], sCB[32];
  __shared__ float P[256], Tm[256], Pp[256], CP[128], S8[64];
  __shared__ float Ai[16], W4[16], Sc4[16], Sci[16], X21[16], X11[16], Sinv[64], KK[128];
  __shared__ float Acc[256], Tmp[256];
  const int t = threadIdx.x;
  const int s = t>>4, j = t&15;

  sA[t]=A_[t]; sQ[t]=Q_[t];
  P[t] = (s==j)?1.f:0.f;
  if (t<128) sC[t]=C_[t];
  if (t<64){ sB[t]=B_[t]; sR[t]=R_[t]; }
  __syncthreads();
  if (t<128){ int o=t>>4, jj=t&15; float a=0.f;
    #pragma unroll
    for(int m=0;m<16;m++) a+=sC[o*16+m]*sA[m*16+jj];
    sCA[t]=a; }
  if (t<32){ int o=t>>2, ii=t&3; float a=0.f;
    #pragma unroll
    for(int m=0;m<16;m++) a+=sC[o*16+m]*sB[m*4+ii];
    sCB[t]=a; }
  __syncthreads();

  for (int k=0;k<RS;k++){
    { float a=0.f;                                    // T = A @ P
      #pragma unroll
      for(int m=0;m<16;m++) a+=sA[s*16+m]*P[m*16+j];
      Tm[t]=a; }
    __syncthreads();
    { float a=sQ[t];                                  // Pp = T A^T + Q
      #pragma unroll
      for(int m=0;m<16;m++) a+=Tm[s*16+m]*sA[j*16+m];
      Pp[t]=a; }
    __syncthreads();
    if (t<128){ int o=t>>4, jj=t&15; float a=0.f;     // CP = C @ Pp
      #pragma unroll
      for(int m=0;m<16;m++) a+=sC[o*16+m]*Pp[m*16+jj];
      CP[t]=a; }
    __syncthreads();
    if (t<64){ int o=t>>3, p=t&7; float a=sR[t];      // S = CP C^T + R
      #pragma unroll
      for(int m=0;m<16;m++) a+=CP[o*16+m]*sC[p*16+m];
      S8[t]=a; }
    __syncthreads();
    inv4(S8, 8, Ai, t);                               // Schur-block inverse of S
    __syncthreads();
    if (t<16){ int i4=t>>2, j4=t&3; float a=0.f;      // W4 = S10 Ai
      #pragma unroll
      for(int m=0;m<4;m++) a+=S8[(4+i4)*8+m]*Ai[m*4+j4];
      W4[t]=a; }
    __syncthreads();
    if (t<16){ int i4=t>>2, j4=t&3;
      float a=S8[(4+i4)*8+4+j4];                      // Sc = S11 - W4 S01
      #pragma unroll
      for(int m=0;m<4;m++) a-=W4[i4*4+m]*S8[m*8+4+j4];
      Sc4[t]=a; }
    __syncthreads();
    inv4(Sc4, 4, Sci, t);
    __syncthreads();
    if (t<16){ int i4=t>>2, j4=t&3; float a=0.f;      // X21 = -Sci W4
      #pragma unroll
      for(int m=0;m<4;m++) a+=Sci[i4*4+m]*W4[m*4+j4];
      X21[t]=-a; }
    __syncthreads();
    if (t<16){ int i4=t>>2, j4=t&3; float a=Ai[t];    // X11 = Ai - W4^T X21
      #pragma unroll
      for(int m=0;m<4;m++) a-=W4[m*4+i4]*X21[m*4+j4];
      X11[t]=a; }
    __syncthreads();
    if (t<64){ int o=t>>3, p=t&7; float v;
      if (o<4 && p<4) v=X11[o*4+p];
      else if (o<4)   v=X21[(p-4)*4+o];
      else if (p<4)   v=X21[(o-4)*4+p];
      else            v=Sci[(o-4)*4+(p-4)];
      Sinv[t]=v; }
    __syncthreads();
    if (t<128){ int ss=t>>3, o=t&7; float a=0.f;      // K = CP^T Sinv
      #pragma unroll
      for(int p=0;p<8;p++) a+=CP[p*16+ss]*Sinv[p*8+o];
      KK[t]=a; }
    __syncthreads();
    { float a=Pp[t], mg=sA[t];                        // P_post, M_k
      #pragma unroll
      for(int o=0;o<8;o++){ float kv=KK[s*8+o]; a-=kv*CP[o*16+j]; mg-=kv*sCA[o*16+j]; }
      P[t]=a;
      g_M[k*256+t]=mg; }
    if (t<128) g_Kg[k*128+t]=KK[t];
    if (t<64){ int ss=t>>2, ii=t&3; float a=sB[t];    // N_k
      #pragma unroll
      for(int o=0;o<8;o++) a-=KK[ss*8+o]*sCB[o*4+ii];
      g_Ng[k*64+t]=a; }
    __syncthreads();
  }

  for (int ph=0; ph<2; ph++){                         // Phi0, Phi1
    int kbase = ph*LCH;
    Acc[t] = g_M[kbase*256 + t];
    __syncthreads();
    for (int i=1;i<LCH;i++){
      const float* Mi = &g_M[(kbase+i)*256];
      float a=0.f;
      #pragma unroll
      for(int m=0;m<16;m++) a+=Mi[s*16+m]*Acc[m*16+j];
      Tmp[t]=a;
      __syncthreads();
      Acc[t]=Tmp[t];
      __syncthreads();
    }
    g_Phi[ph*256+t]=Acc[t];
    __syncthreads();
  }
  Acc[t]=g_M[(RS-1)*256+t];
  __syncthreads();
  for (int q=0;q<4;q++){                              // Phi_ss = M_ss^16
    float a=0.f;
    #pragma unroll
    for(int m=0;m<16;m++) a+=Acc[s*16+m]*Acc[m*16+j];
    Tmp[t]=a;
    __syncthreads();
    Acc[t]=Tmp[t];
    __syncthreads();
  }
  g_Phi[2*256+t]=Acc[t];
}

// P1/P3: LCH steps per (batch,chunk). PHASE1: zero init, store g_d. PHASE3: init g_xs, write out.
template<int PHASE>
__global__ void __launch_bounds__(TPB) pass_kernel(const float* __restrict__ obs,
                                                   const float* __restrict__ u,
                                                   float* __restrict__ out)
{
  const int c  = blockIdx.y;
  const int b0 = (blockIdx.x*TPB + threadIdx.x)*NB;
  float x[NB][SDIM];
  if (PHASE==1){
    #pragma unroll
    for (int nb=0;nb<NB;nb++)
      #pragma unroll
      for (int s=0;s<SDIM;s++) x[nb][s]=0.f;
  } else {
    #pragma unroll
    for (int nb=0;nb<NB;nb++){
      const float* xp = &g_xs[((size_t)c*BATCH + (size_t)(b0+nb))*SDIM];
      #pragma unroll
      for (int s=0;s<SDIM;s++) x[nb][s]=xp[s];
    }
  }
  const int k0 = c*LCH;
  for (int i=0;i<LCH;i++){
    const int k  = k0+i;
    const int kk = (k < RS) ? k : (RS-1);
    const float* __restrict__ Mk = &g_M [kk*SDIM*SDIM];
    const float* __restrict__ Kk = &g_Kg[kk*SDIM*ODIM];
    const float* __restrict__ Nk = &g_Ng[kk*SDIM*IDIM];
    float4 za[NB], zb[NB], uu[NB];
    #pragma unroll
    for (int nb=0;nb<NB;nb++){
      const float4* zp = reinterpret_cast<const float4*>(obs + ((size_t)(b0+nb)*T_SEQ + k)*ODIM);
      za[nb]=zp[0]; zb[nb]=zp[1];
      uu[nb]=*reinterpret_cast<const float4*>(u + ((size_t)(b0+nb)*T_SEQ + k)*IDIM);
    }
    float xn[NB][SDIM];
    #pragma unroll
    for (int s=0;s<SDIM;s++){
      float acc[NB];
      #pragma unroll
      for (int nb=0;nb<NB;nb++){
        acc[nb] = Kk[s*ODIM+0]*za[nb].x + Kk[s*ODIM+1]*za[nb].y
                + Kk[s*ODIM+2]*za[nb].z + Kk[s*ODIM+3]*za[nb].w
                + Kk[s*ODIM+4]*zb[nb].x + Kk[s*ODIM+5]*zb[nb].y
                + Kk[s*ODIM+6]*zb[nb].z + Kk[s*ODIM+7]*zb[nb].w
                + Nk[s*IDIM+0]*uu[nb].x + Nk[s*IDIM+1]*uu[nb].y
                + Nk[s*IDIM+2]*uu[nb].z + Nk[s*IDIM+3]*uu[nb].w;
      }
      #pragma unroll
      for (int jj=0;jj<SDIM;jj++){
        const float m = Mk[s*SDIM+jj];
        #pragma unroll
        for (int nb=0;nb<NB;nb++) acc[nb] += m*x[nb][jj];
      }
      #pragma unroll
      for (int nb=0;nb<NB;nb++) xn[nb][s]=acc[nb];
    }
    #pragma unroll
    for (int nb=0;nb<NB;nb++)
      #pragma unroll
      for (int s=0;s<SDIM;s++) x[nb][s]=xn[nb][s];
    if (PHASE==3){
      #pragma unroll
      for (int nb=0;nb<NB;nb++){
        float4* op = reinterpret_cast<float4*>(out + (((size_t)(b0+nb)*T_SEQ) + k)*SDIM);
        op[0]=make_float4(x[nb][0], x[nb][1], x[nb][2], x[nb][3]);
        op[1]=make_float4(x[nb][4], x[nb][5], x[nb][6], x[nb][7]);
        op[2]=make_float4(x[nb][8], x[nb][9], x[nb][10],x[nb][11]);
        op[3]=make_float4(x[nb][12],x[nb][13],x[nb][14],x[nb][15]);
      }
    }
  }
  if (PHASE==1){
    #pragma unroll
    for (int nb=0;nb<NB;nb++){
      float* dp = &g_d[((size_t)c*BATCH + (size_t)(b0+nb))*SDIM];
      #pragma unroll
      for (int s=0;s<SDIM;s++) dp[s]=x[nb][s];
    }
  }
}

// P2: exact serial combine across chunks, one thread per batch.
__global__ void __launch_bounds__(TPB) pass2_kernel(const float* __restrict__ x0)
{
  const int b = blockIdx.x*TPB + threadIdx.x;
  float x[16];
  #pragma unroll
  for(int s=0;s<16;s++) x[s]=x0[s];
  {
    float* xp=&g_xs[(size_t)b*16];
    #pragma unroll
    for(int s=0;s<16;s++) xp[s]=x[s];
  }
  for (int c=1;c<CH;c++){
    const float* Phi=&g_Phi[((c-1)<2?(c-1):2)*256];
    const float* dd =&g_d[((size_t)(c-1)*BATCH+(size_t)b)*16];
    float xn[16];
    #pragma unroll
    for(int s=0;s<16;s++){
      float a=dd[s];
      #pragma unroll
      for(int jj=0;jj<16;jj++) a+=Phi[s*16+jj]*x[jj];
      xn[s]=a;
    }
    #pragma unroll
    for(int s=0;s<16;s++) x[s]=xn[s];
    float* xp=&g_xs[((size_t)c*BATCH+(size_t)b)*16];
    #pragma unroll
    for(int s=0;s<16;s++) xp[s]=x[s];
  }
}

extern "C" void kernel_launch(void* const* d_in, const int* in_sizes, int n_in,
                              void* d_out, int out_size)
{
  const float* obs = (const float*)d_in[0];
  const float* u   = (const float*)d_in[1];
  const float* A   = (const float*)d_in[2];
  const float* B   = (const float*)d_in[3];
  const float* C   = (const float*)d_in[4];
  const float* Q   = (const float*)d_in[5];
  const float* R   = (const float*)d_in[6];
  const float* x0  = (const float*)d_in[7];
  float* out = (float*)d_out;

  riccati_kernel<<<1, 256>>>(A, B, C, Q, R);

  dim3 grid1(BATCH/(TPB*NB), CH);
  pass_kernel<1><<<grid1, TPB>>>(obs, u, out);
  pass2_kernel<<<BATCH/TPB, TPB>>>(x0);
  pass_kernel<3><<<grid1, TPB>>>(obs, u, out);
}

// round 3
// speedup vs baseline: 1.0171x; 1.0171x over previous
#include <cuda_runtime.h>
#include <cstdint>
#include <cstddef>

#define BATCH 4096
#define T_SEQ 512
#define SDIM  16
#define ODIM  8
#define IDIM  4
#define RS    32
#define CH    64
#define LCH   8
#define NB    2
#define TPB   128
#define NPHI  5

typedef unsigned long long ull;

__device__ float g_M [RS*256];
__device__ float g_Kg[RS*128];
__device__ float g_Ng[RS*64];
__device__ float g_Phi[NPHI*256];
__device__ float g_d [(size_t)CH*BATCH*SDIM];
__device__ float g_xs[(size_t)CH*BATCH*SDIM];

// ---------- f32x2 helpers ----------
__device__ __forceinline__ ull fpair(float a, float b){
  ull r; asm("mov.b64 %0, {%1,%2};" : "=l"(r) : "f"(a), "f"(b)); return r;
}
__device__ __forceinline__ ull fdup(float a){ return fpair(a,a); }
__device__ __forceinline__ void unpack2(ull p, float& a, float& b){
  asm("mov.b64 {%0,%1}, %2;" : "=f"(a), "=f"(b) : "l"(p));
}
__device__ __forceinline__ ull fmul2(ull a, ull b){
  ull r; asm("mul.rn.f32x2 %0, %1, %2;" : "=l"(r) : "l"(a), "l"(b)); return r;
}
__device__ __forceinline__ void ffma2(ull& d, ull a, ull b){
  asm("fma.rn.f32x2 %0, %1, %2, %0;" : "+l"(d) : "l"(a), "l"(b));
}

// ---------- 4x4 SPD inverse (adjugate) ----------
__device__ __forceinline__ float det3v(float a00,float a01,float a02,
                                       float a10,float a11,float a12,
                                       float a20,float a21,float a22){
  return a00*(a11*a22-a12*a21)-a01*(a10*a22-a12*a20)+a02*(a10*a21-a11*a20);
}
__device__ __forceinline__ float minor3(const float* M,int ld,int r,int c){
  int rs[3],cs[3]; int q=0;
  for(int a=0;a<4;a++) if(a!=r) rs[q++]=a;
  q=0;
  for(int a=0;a<4;a++) if(a!=c) cs[q++]=a;
  return det3v(M[rs[0]*ld+cs[0]],M[rs[0]*ld+cs[1]],M[rs[0]*ld+cs[2]],
               M[rs[1]*ld+cs[0]],M[rs[1]*ld+cs[1]],M[rs[1]*ld+cs[2]],
               M[rs[2]*ld+cs[0]],M[rs[2]*ld+cs[1]],M[rs[2]*ld+cs[2]]);
}
__device__ __forceinline__ void inv4(const float* M,int ld,float* inv,int t){
  if (t<16){
    int i=t>>2, j=t&3;
    float det=0.f;
    for(int r=0;r<4;r++){
      float sgn=(r&1)?-1.f:1.f;
      det += sgn*M[r*ld]*minor3(M,ld,r,0);
    }
    float cof=(((i+j)&1)?-1.f:1.f)*minor3(M,ld,j,i);
    inv[i*4+j]=cof/det;
  }
}

// K1: batch-independent Riccati + chunk propagators. 1 block, 256 threads.
__global__ void riccati_kernel(const float* __restrict__ A_, const float* __restrict__ B_,
                               const float* __restrict__ C_, const float* __restrict__ Q_,
                               const float* __restrict__ R_)
{
  __shared__ float sA[256], sQ[256], sC[128], sB[64], sR[64], sCA[128], sCB[32];
  __shared__ float P[256], Tm[256], Pp[256], CP[128], S8[64];
  __shared__ float Ai[16], W4[16], Sc4[16], Sci[16], X21[16], X11[16], Sinv[64], KK[128];
  __shared__ float BufA[256], BufB[256];
  const int t = threadIdx.x;
  const int s = t>>4, j = t&15;

  sA[t]=A_[t]; sQ[t]=Q_[t];
  P[t] = (s==j)?1.f:0.f;
  if (t<128) sC[t]=C_[t];
  if (t<64){ sB[t]=B_[t]; sR[t]=R_[t]; }
  __syncthreads();
  if (t<128){ int o=t>>4, jj=t&15; float a=0.f;
    #pragma unroll
    for(int m=0;m<16;m++) a+=sC[o*16+m]*sA[m*16+jj];
    sCA[t]=a; }
  if (t<32){ int o=t>>2, ii=t&3; float a=0.f;
    #pragma unroll
    for(int m=0;m<16;m++) a+=sC[o*16+m]*sB[m*4+ii];
    sCB[t]=a; }
  __syncthreads();

  for (int k=0;k<RS;k++){
    { float a=0.f;                                    // Tm = A @ P
      #pragma unroll
      for(int m=0;m<16;m++) a+=sA[s*16+m]*P[m*16+j];
      Tm[t]=a; }
    __syncthreads();
    { float a=sQ[t];                                  // Pp = Tm A^T + Q
      #pragma unroll
      for(int m=0;m<16;m++) a+=Tm[s*16+m]*sA[j*16+m];
      Pp[t]=a; }
    __syncthreads();
    if (t<128){ int o=t>>4, jj=t&15; float a=0.f;     // CP = C @ Pp
      #pragma unroll
      for(int m=0;m<16;m++) a+=sC[o*16+m]*Pp[m*16+jj];
      CP[t]=a; }
    __syncthreads();
    if (t<64){ int o=t>>3, p=t&7; float a=sR[t];      // S = CP C^T + R
      #pragma unroll
      for(int m=0;m<16;m++) a+=CP[o*16+m]*sC[p*16+m];
      S8[t]=a; }
    __syncthreads();
    if (t<32){                                        // warp 0: invert S (Schur blocks)
      inv4(S8, 8, Ai, t);
      __syncwarp();
      if (t<16){ int i4=t>>2, j4=t&3; float a=0.f;    // W4 = S10 Ai
        #pragma unroll
        for(int m=0;m<4;m++) a+=S8[(4+i4)*8+m]*Ai[m*4+j4];
        W4[t]=a; }
      __syncwarp();
      if (t<16){ int i4=t>>2, j4=t&3;
        float a=S8[(4+i4)*8+4+j4];                    // Sc = S11 - W4 S01
        #pragma unroll
        for(int m=0;m<4;m++) a-=W4[i4*4+m]*S8[m*8+4+j4];
        Sc4[t]=a; }
      __syncwarp();
      inv4(Sc4, 4, Sci, t);
      __syncwarp();
      if (t<16){ int i4=t>>2, j4=t&3; float a=0.f;    // X21 = -Sci W4
        #pragma unroll
        for(int m=0;m<4;m++) a+=Sci[i4*4+m]*W4[m*4+j4];
        X21[t]=-a; }
      __syncwarp();
      if (t<16){ int i4=t>>2, j4=t&3; float a=Ai[t];  // X11 = Ai - W4^T X21
        #pragma unroll
        for(int m=0;m<4;m++) a-=W4[m*4+i4]*X21[m*4+j4];
        X11[t]=a; }
      __syncwarp();
      for (int e=t; e<64; e+=32){ int o=e>>3, p=e&7; float v;
        if (o<4 && p<4) v=X11[o*4+p];
        else if (o<4)   v=X21[(p-4)*4+o];
        else if (p<4)   v=X21[(o-4)*4+p];
        else            v=Sci[(o-4)*4+(p-4)];
        Sinv[e]=v; }
    }
    __syncthreads();
    if (t<128){ int ss=t>>3, o=t&7; float a=0.f;      // K = CP^T Sinv
      #pragma unroll
      for(int p=0;p<8;p++) a+=CP[p*16+ss]*Sinv[p*8+o];
      KK[t]=a; }
    __syncthreads();
    { float a=Pp[t], mg=sA[t];                        // P_post, M_k
      #pragma unroll
      for(int o=0;o<8;o++){ float kv=KK[s*8+o]; a-=kv*CP[o*16+j]; mg-=kv*sCA[o*16+j]; }
      P[t]=a;
      g_M[k*256+t]=mg; }
    if (t<128) g_Kg[k*128+t]=KK[t];
    if (t<64){ int ss=t>>2, ii=t&3; float a=sB[t];    // N_k
      #pragma unroll
      for(int o=0;o<8;o++) a-=KK[ss*8+o]*sCB[o*4+ii];
      g_Ng[k*64+t]=a; }
    __syncthreads();
  }

  // Phi[ph] = product of M over chunk ph (ph = 0..3, covering k<32)
  float* bA = BufA; float* bB = BufB;
  for (int ph=0; ph<4; ph++){
    int kbase = ph*LCH;
    bA[t] = g_M[kbase*256 + t];
    __syncthreads();
    for (int i=1;i<LCH;i++){
      const float* Mi = &g_M[(kbase+i)*256];
      float a=0.f;
      #pragma unroll
      for(int m=0;m<16;m++) a+=Mi[s*16+m]*bA[m*16+j];
      bB[t]=a;
      __syncthreads();
      float* tmp=bA; bA=bB; bB=tmp;
    }
    g_Phi[ph*256+t]=bA[t];
    __syncthreads();
  }
  // Phi[4] = M_ss^LCH via 3 squarings
  bA[t]=g_M[(RS-1)*256+t];
  __syncthreads();
  for (int q=0;q<3;q++){
    float a=0.f;
    #pragma unroll
    for(int m=0;m<16;m++) a+=bA[s*16+m]*bA[m*16+j];
    bB[t]=a;
    __syncthreads();
    float* tmp=bA; bA=bB; bB=tmp;
    __syncthreads();
  }
  g_Phi[4*256+t]=bA[t];
}

// P1/P3: LCH steps per (batch-pair, chunk) with f32x2 packed math.
template<int PHASE>
__global__ void __launch_bounds__(TPB) pass_kernel(const float* __restrict__ obs,
                                                   const float* __restrict__ u,
                                                   float* __restrict__ out)
{
  __shared__ ull sM[LCH*256];   // (m,m) duplicated pairs
  __shared__ ull sK[LCH*128];
  __shared__ ull sN[LCH*64];
  const int c  = blockIdx.y;
  const int k0 = c*LCH;
  for (int idx = threadIdx.x; idx < LCH*256; idx += TPB){
    int i = idx >> 8, e = idx & 255;
    int kk = k0+i; if (kk > RS-1) kk = RS-1;
    sM[idx] = fdup(g_M[kk*256+e]);
  }
  for (int idx = threadIdx.x; idx < LCH*128; idx += TPB){
    int i = idx >> 7, e = idx & 127;
    int kk = k0+i; if (kk > RS-1) kk = RS-1;
    sK[idx] = fdup(g_Kg[kk*128+e]);
  }
  for (int idx = threadIdx.x; idx < LCH*64; idx += TPB){
    int i = idx >> 6, e = idx & 63;
    int kk = k0+i; if (kk > RS-1) kk = RS-1;
    sN[idx] = fdup(g_Ng[kk*64+e]);
  }
  const int b0 = (blockIdx.x*TPB + threadIdx.x)*NB;
  ull xp[SDIM];
  if (PHASE==1){
    #pragma unroll
    for (int s=0;s<SDIM;s++) xp[s]=0ull;
  } else {
    const float* x0p = &g_xs[((size_t)c*BATCH + (size_t)b0)*SDIM];
    #pragma unroll
    for (int s=0;s<SDIM;s++) xp[s]=fpair(x0p[s], x0p[SDIM+s]);
  }
  __syncthreads();

  const float* ob0 = obs + ((size_t)b0*T_SEQ + k0)*ODIM;
  const float* ob1 = ob0 + (size_t)T_SEQ*ODIM;
  const float* uu0 = u   + ((size_t)b0*T_SEQ + k0)*IDIM;
  const float* uu1 = uu0 + (size_t)T_SEQ*IDIM;

  for (int i=0;i<LCH;i++){
    float4 z0a = *(const float4*)(ob0 + i*ODIM);
    float4 z0b = *(const float4*)(ob0 + i*ODIM + 4);
    float4 z1a = *(const float4*)(ob1 + i*ODIM);
    float4 z1b = *(const float4*)(ob1 + i*ODIM + 4);
    float4 v0  = *(const float4*)(uu0 + i*IDIM);
    float4 v1  = *(const float4*)(uu1 + i*IDIM);
    ull zp[8], up[4];
    zp[0]=fpair(z0a.x,z1a.x); zp[1]=fpair(z0a.y,z1a.y);
    zp[2]=fpair(z0a.z,z1a.z); zp[3]=fpair(z0a.w,z1a.w);
    zp[4]=fpair(z0b.x,z1b.x); zp[5]=fpair(z0b.y,z1b.y);
    zp[6]=fpair(z0b.z,z1b.z); zp[7]=fpair(z0b.w,z1b.w);
    up[0]=fpair(v0.x,v1.x);   up[1]=fpair(v0.y,v1.y);
    up[2]=fpair(v0.z,v1.z);   up[3]=fpair(v0.w,v1.w);

    const ulonglong2* M2 = (const ulonglong2*)&sM[i*256];
    const ulonglong2* K2 = (const ulonglong2*)&sK[i*128];
    const ulonglong2* N2 = (const ulonglong2*)&sN[i*64];
    ull xn[SDIM];
    #pragma unroll
    for (int s=0;s<SDIM;s++){
      ulonglong2 k0p = K2[s*4+0];
      ull acc = fmul2(k0p.x, zp[0]);
      ffma2(acc, k0p.y, zp[1]);
      ulonglong2 k1p = K2[s*4+1]; ffma2(acc, k1p.x, zp[2]); ffma2(acc, k1p.y, zp[3]);
      ulonglong2 k2p = K2[s*4+2]; ffma2(acc, k2p.x, zp[4]); ffma2(acc, k2p.y, zp[5]);
      ulonglong2 k3p = K2[s*4+3]; ffma2(acc, k3p.x, zp[6]); ffma2(acc, k3p.y, zp[7]);
      ulonglong2 n0p = N2[s*2+0]; ffma2(acc, n0p.x, up[0]); ffma2(acc, n0p.y, up[1]);
      ulonglong2 n1p = N2[s*2+1]; ffma2(acc, n1p.x, up[2]); ffma2(acc, n1p.y, up[3]);
      #pragma unroll
      for (int jj=0;jj<8;jj++){
        ulonglong2 mm = M2[s*8+jj];
        ffma2(acc, mm.x, xp[2*jj]);
        ffma2(acc, mm.y, xp[2*jj+1]);
      }
      xn[s]=acc;
    }
    #pragma unroll
    for (int s=0;s<SDIM;s++) xp[s]=xn[s];

    if (PHASE==3){
      float a0[SDIM], a1[SDIM];
      #pragma unroll
      for (int s=0;s<SDIM;s++) unpack2(xp[s], a0[s], a1[s]);
      float4* o0 = (float4*)(out + (((size_t)b0*T_SEQ) + (size_t)(k0+i))*SDIM);
      float4* o1 = (float4*)(out + (((size_t)(b0+1)*T_SEQ) + (size_t)(k0+i))*SDIM);
      o0[0]=make_float4(a0[0],a0[1],a0[2],a0[3]);
      o0[1]=make_float4(a0[4],a0[5],a0[6],a0[7]);
      o0[2]=make_float4(a0[8],a0[9],a0[10],a0[11]);
      o0[3]=make_float4(a0[12],a0[13],a0[14],a0[15]);
      o1[0]=make_float4(a1[0],a1[1],a1[2],a1[3]);
      o1[1]=make_float4(a1[4],a1[5],a1[6],a1[7]);
      o1[2]=make_float4(a1[8],a1[9],a1[10],a1[11]);
      o1[3]=make_float4(a1[12],a1[13],a1[14],a1[15]);
    }
  }
  if (PHASE==1){
    float a0[SDIM], a1[SDIM];
    #pragma unroll
    for (int s=0;s<SDIM;s++) unpack2(xp[s], a0[s], a1[s]);
    float4* d0 = (float4*)&g_d[((size_t)c*BATCH+(size_t)b0)*SDIM];
    d0[0]=make_float4(a0[0],a0[1],a0[2],a0[3]);
    d0[1]=make_float4(a0[4],a0[5],a0[6],a0[7]);
    d0[2]=make_float4(a0[8],a0[9],a0[10],a0[11]);
    d0[3]=make_float4(a0[12],a0[13],a0[14],a0[15]);
    d0[4]=make_float4(a1[0],a1[1],a1[2],a1[3]);
    d0[5]=make_float4(a1[4],a1[5],a1[6],a1[7]);
    d0[6]=make_float4(a1[8],a1[9],a1[10],a1[11]);
    d0[7]=make_float4(a1[12],a1[13],a1[14],a1[15]);
  }
}

// P2: exact serial combine across chunks, one thread per batch.
__global__ void __launch_bounds__(TPB) pass2_kernel(const float* __restrict__ x0)
{
  const int b = blockIdx.x*TPB + threadIdx.x;
  float x[16];
  #pragma unroll
  for(int s=0;s<16;s++) x[s]=x0[s];
  {
    float* xp=&g_xs[(size_t)b*16];
    #pragma unroll
    for(int s=0;s<16;s++) xp[s]=x[s];
  }
  for (int c=1;c<CH;c++){
    int pidx = c-1; if (pidx > NPHI-1) pidx = NPHI-1;
    const float* Phi=&g_Phi[pidx*256];
    const float* dd =&g_d[((size_t)(c-1)*BATCH+(size_t)b)*16];
    float xn[16];
    #pragma unroll
    for(int s=0;s<16;s++){
      float a=dd[s];
      #pragma unroll
      for(int jj=0;jj<16;jj++) a+=Phi[s*16+jj]*x[jj];
      xn[s]=a;
    }
    #pragma unroll
    for(int s=0;s<16;s++) x[s]=xn[s];
    float* xp=&g_xs[((size_t)c*BATCH+(size_t)b)*16];
    #pragma unroll
    for(int s=0;s<16;s++) xp[s]=x[s];
  }
}

extern "C" void kernel_launch(void* const* d_in, const int* in_sizes, int n_in,
                              void* d_out, int out_size)
{
  const float* obs = (const float*)d_in[0];
  const float* u   = (const float*)d_in[1];
  const float* A   = (const float*)d_in[2];
  const float* B   = (const float*)d_in[3];
  const float* C   = (const float*)d_in[4];
  const float* Q   = (const float*)d_in[5];
  const float* R   = (const float*)d_in[6];
  const float* x0  = (const float*)d_in[7];
  float* out = (float*)d_out;

  riccati_kernel<<<1, 256>>>(A, B, C, Q, R);

  dim3 grid1(BATCH/(TPB*NB), CH);
  pass_kernel<1><<<grid1, TPB>>>(obs, u, out);
  pass2_kernel<<<BATCH/TPB, TPB>>>(x0);
  pass_kernel<3><<<grid1, TPB>>>(obs, u, out);
}

// round 4
// speedup vs baseline: 1.3812x; 1.3580x over previous
#include <cuda_runtime.h>
#include <cstdint>
#include <cstddef>

#define BATCH 4096
#define T_SEQ 512
#define SDIM  16
#define ODIM  8
#define IDIM  4
#define RS    16
#define CH    64
#define LCH   8
#define NB    2
#define TPB   128
#define NPHI  3

typedef unsigned long long ull;

__device__ float g_M [RS*256];
__device__ float g_Kg[RS*128];
__device__ float g_Ng[RS*64];
__device__ float g_Phi[NPHI*256];
__device__ float g_d [(size_t)CH*SDIM*BATCH];   // [c][s][b]
__device__ float g_xs[(size_t)CH*SDIM*BATCH];   // [c][s][b]

// ---------- f32x2 helpers ----------
__device__ __forceinline__ ull fpair(float a, float b){
  ull r; asm("mov.b64 %0, {%1,%2};" : "=l"(r) : "f"(a), "f"(b)); return r;
}
__device__ __forceinline__ ull fdup(float a){ return fpair(a,a); }
__device__ __forceinline__ void unpack2(ull p, float& a, float& b){
  asm("mov.b64 {%0,%1}, %2;" : "=f"(a), "=f"(b) : "l"(p));
}
__device__ __forceinline__ ull fmul2(ull a, ull b){
  ull r; asm("mul.rn.f32x2 %0, %1, %2;" : "=l"(r) : "l"(a), "l"(b)); return r;
}
__device__ __forceinline__ void ffma2(ull& d, ull a, ull b){
  asm("fma.rn.f32x2 %0, %1, %2, %0;" : "+l"(d) : "l"(a), "l"(b));
}

// ---------- fully unrolled 4x4 inverse (adjugate, s/c-factor form) ----------
__device__ __forceinline__ void inv4x4(const float* m, int ld, float* inv){
  float a00=m[0],      a01=m[1],      a02=m[2],      a03=m[3];
  float a10=m[ld],     a11=m[ld+1],   a12=m[ld+2],   a13=m[ld+3];
  float a20=m[2*ld],   a21=m[2*ld+1], a22=m[2*ld+2], a23=m[2*ld+3];
  float a30=m[3*ld],   a31=m[3*ld+1], a32=m[3*ld+2], a33=m[3*ld+3];
  float s0=a00*a11-a01*a10, s1=a00*a12-a02*a10, s2=a00*a13-a03*a10;
  float s3=a01*a12-a02*a11, s4=a01*a13-a03*a11, s5=a02*a13-a03*a12;
  float c5=a22*a33-a23*a32, c4=a21*a33-a23*a31, c3=a21*a32-a22*a31;
  float c2=a20*a33-a23*a30, c1=a20*a32-a22*a30, c0=a20*a31-a21*a30;
  float det=s0*c5-s1*c4+s2*c3+s3*c2-s4*c1+s5*c0;
  float id=1.f/det;
  inv[0] =( a11*c5-a12*c4+a13*c3)*id;
  inv[1] =(-a01*c5+a02*c4-a03*c3)*id;
  inv[2] =( a31*s5-a32*s4+a33*s3)*id;
  inv[3] =(-a21*s5+a22*s4-a23*s3)*id;
  inv[4] =(-a10*c5+a12*c2-a13*c1)*id;
  inv[5] =( a00*c5-a02*c2+a03*c1)*id;
  inv[6] =(-a30*s5+a32*s2-a33*s1)*id;
  inv[7] =( a20*s5-a22*s2+a23*s1)*id;
  inv[8] =( a10*c4-a11*c2+a13*c0)*id;
  inv[9] =(-a00*c4+a01*c2-a03*c0)*id;
  inv[10]=( a30*s4-a31*s2+a33*s0)*id;
  inv[11]=(-a20*s4+a21*s2-a23*s0)*id;
  inv[12]=(-a10*c3+a11*c1-a12*c0)*id;
  inv[13]=( a00*c3-a01*c1+a02*c0)*id;
  inv[14]=(-a30*s3+a31*s1-a32*s0)*id;
  inv[15]=( a20*s3-a21*s1+a22*s0)*id;
}

// K1: batch-independent Riccati + chunk propagators. 1 block, 256 threads.
__global__ void riccati_kernel(const float* __restrict__ A_, const float* __restrict__ B_,
                               const float* __restrict__ C_, const float* __restrict__ Q_,
                               const float* __restrict__ R_)
{
  __shared__ float sA[256], sQ[256], sC[128], sB[64], sR[64], sCA[128], sCB[32];
  __shared__ float P[256], Tm[256], Pp[256], CP[128], S8[64], Sinv[64], KK[128];
  __shared__ float BufA[256], BufB[256];
  const int t = threadIdx.x;
  const int s = t>>4, j = t&15;

  sA[t]=A_[t]; sQ[t]=Q_[t];
  P[t] = (s==j)?1.f:0.f;
  if (t<128) sC[t]=C_[t];
  if (t<64){ sB[t]=B_[t]; sR[t]=R_[t]; }
  __syncthreads();
  if (t<128){ int o=t>>4, jj=t&15; float a=0.f;
    #pragma unroll
    for(int m=0;m<16;m++) a+=sC[o*16+m]*sA[m*16+jj];
    sCA[t]=a; }
  if (t<32){ int o=t>>2, ii=t&3; float a=0.f;
    #pragma unroll
    for(int m=0;m<16;m++) a+=sC[o*16+m]*sB[m*4+ii];
    sCB[t]=a; }
  __syncthreads();

  for (int k=0;k<RS;k++){
    { float a=0.f;                                    // Tm = A @ P
      #pragma unroll
      for(int m=0;m<16;m++) a+=sA[s*16+m]*P[m*16+j];
      Tm[t]=a; }
    __syncthreads();
    { float a=sQ[t];                                  // Pp = Tm A^T + Q
      #pragma unroll
      for(int m=0;m<16;m++) a+=Tm[s*16+m]*sA[j*16+m];
      Pp[t]=a; }
    __syncthreads();
    if (t<128){ int o=t>>4, jj=t&15; float a=0.f;     // CP = C @ Pp
      #pragma unroll
      for(int m=0;m<16;m++) a+=sC[o*16+m]*Pp[m*16+jj];
      CP[t]=a; }
    __syncthreads();
    if (t<64){ int o=t>>3, p=t&7; float a=sR[t];      // S = CP C^T + R
      #pragma unroll
      for(int m=0;m<16;m++) a+=CP[o*16+m]*sC[p*16+m];
      S8[t]=a; }
    __syncthreads();
    if (t==0){                                        // 8x8 SPD inverse via Schur, in registers
      float Ai[16]; inv4x4(&S8[0], 8, Ai);
      float W[16];
      #pragma unroll
      for(int i4=0;i4<4;i4++)
        #pragma unroll
        for(int j4=0;j4<4;j4++){ float a=0.f;
          #pragma unroll
          for(int m=0;m<4;m++) a+=S8[(4+i4)*8+m]*Ai[m*4+j4];
          W[i4*4+j4]=a; }
      float Sc[16];
      #pragma unroll
      for(int i4=0;i4<4;i4++)
        #pragma unroll
        for(int j4=0;j4<4;j4++){ float a=S8[(4+i4)*8+4+j4];
          #pragma unroll
          for(int m=0;m<4;m++) a-=W[i4*4+m]*S8[m*8+4+j4];
          Sc[i4*4+j4]=a; }
      float Sci[16]; inv4x4(Sc, 4, Sci);
      float X21[16];
      #pragma unroll
      for(int i4=0;i4<4;i4++)
        #pragma unroll
        for(int j4=0;j4<4;j4++){ float a=0.f;
          #pragma unroll
          for(int m=0;m<4;m++) a+=Sci[i4*4+m]*W[m*4+j4];
          X21[i4*4+j4]=-a; }
      float X11[16];
      #pragma unroll
      for(int i4=0;i4<4;i4++)
        #pragma unroll
        for(int j4=0;j4<4;j4++){ float a=Ai[i4*4+j4];
          #pragma unroll
          for(int m=0;m<4;m++) a-=W[m*4+i4]*X21[m*4+j4];
          X11[i4*4+j4]=a; }
      #pragma unroll
      for(int o=0;o<8;o++)
        #pragma unroll
        for(int p=0;p<8;p++){
          float v;
          if (o<4 && p<4) v=X11[o*4+p];
          else if (o<4)   v=X21[(p-4)*4+o];
          else if (p<4)   v=X21[(o-4)*4+p];
          else            v=Sci[(o-4)*4+(p-4)];
          Sinv[o*8+p]=v; }
    }
    __syncthreads();
    if (t<128){ int ss=t>>3, o=t&7; float a=0.f;      // K = CP^T Sinv
      #pragma unroll
      for(int p=0;p<8;p++) a+=CP[p*16+ss]*Sinv[p*8+o];
      KK[t]=a; }
    __syncthreads();
    { float a=Pp[t], mg=sA[t];                        // P_post, M_k
      #pragma unroll
      for(int o=0;o<8;o++){ float kv=KK[s*8+o]; a-=kv*CP[o*16+j]; mg-=kv*sCA[o*16+j]; }
      P[t]=a;
      g_M[k*256+t]=mg; }
    if (t<128) g_Kg[k*128+t]=KK[t];
    if (t<64){ int ss=t>>2, ii=t&3; float a=sB[t];    // N_k
      #pragma unroll
      for(int o=0;o<8;o++) a-=KK[ss*8+o]*sCB[o*4+ii];
      g_Ng[k*64+t]=a; }
    __syncthreads();
  }

  // Phi0 = M7..M0 ; Phi1 = M15..M8 ; Phi2 = M15^8
  float* bA = BufA; float* bB = BufB;
  for (int ph=0; ph<2; ph++){
    int kbase = ph*LCH;
    bA[t] = g_M[kbase*256 + t];
    __syncthreads();
    for (int i=1;i<LCH;i++){
      const float* Mi = &g_M[(kbase+i)*256];
      float a=0.f;
      #pragma unroll
      for(int m=0;m<16;m++) a+=Mi[s*16+m]*bA[m*16+j];
      bB[t]=a;
      __syncthreads();
      float* tmp=bA; bA=bB; bB=tmp;
    }
    g_Phi[ph*256+t]=bA[t];
    __syncthreads();
  }
  bA[t]=g_M[(RS-1)*256+t];
  __syncthreads();
  for (int q=0;q<3;q++){
    float a=0.f;
    #pragma unroll
    for(int m=0;m<16;m++) a+=bA[s*16+m]*bA[m*16+j];
    bB[t]=a;
    __syncthreads();
    float* tmp=bA; bA=bB; bB=tmp;
    __syncthreads();
  }
  g_Phi[2*256+t]=bA[t];
}

// P1/P3: LCH steps per (batch-pair, chunk) with f32x2 packed math.
template<int PHASE>
__global__ void __launch_bounds__(TPB, 5) pass_kernel(const float* __restrict__ obs,
                                                      const float* __restrict__ u,
                                                      float* __restrict__ out)
{
  __shared__ ull sM[LCH*256];
  __shared__ ull sK[LCH*128];
  __shared__ ull sN[LCH*64];
  const int c  = blockIdx.y;
  const int k0 = c*LCH;
  for (int idx = threadIdx.x; idx < LCH*256; idx += TPB){
    int i = idx >> 8, e = idx & 255;
    int kk = k0+i; if (kk > RS-1) kk = RS-1;
    sM[idx] = fdup(g_M[kk*256+e]);
  }
  for (int idx = threadIdx.x; idx < LCH*128; idx += TPB){
    int i = idx >> 7, e = idx & 127;
    int kk = k0+i; if (kk > RS-1) kk = RS-1;
    sK[idx] = fdup(g_Kg[kk*128+e]);
  }
  for (int idx = threadIdx.x; idx < LCH*64; idx += TPB){
    int i = idx >> 6, e = idx & 63;
    int kk = k0+i; if (kk > RS-1) kk = RS-1;
    sN[idx] = fdup(g_Ng[kk*64+e]);
  }
  const int b0 = (blockIdx.x*TPB + threadIdx.x)*NB;
  ull xp[SDIM];
  if (PHASE==1){
    #pragma unroll
    for (int s=0;s<SDIM;s++) xp[s]=0ull;
  } else {
    #pragma unroll
    for (int s=0;s<SDIM;s++)
      xp[s] = *(const ull*)&g_xs[((size_t)(c*SDIM+s))*BATCH + b0];
  }
  __syncthreads();

  const float* ob0 = obs + ((size_t)b0*T_SEQ + k0)*ODIM;
  const float* ob1 = ob0 + (size_t)T_SEQ*ODIM;
  const float* uu0 = u   + ((size_t)b0*T_SEQ + k0)*IDIM;
  const float* uu1 = uu0 + (size_t)T_SEQ*IDIM;

  for (int i=0;i<LCH;i++){
    float4 z0a = *(const float4*)(ob0 + i*ODIM);
    float4 z0b = *(const float4*)(ob0 + i*ODIM + 4);
    float4 z1a = *(const float4*)(ob1 + i*ODIM);
    float4 z1b = *(const float4*)(ob1 + i*ODIM + 4);
    float4 v0  = *(const float4*)(uu0 + i*IDIM);
    float4 v1  = *(const float4*)(uu1 + i*IDIM);
    ull zp[8], up[4];
    zp[0]=fpair(z0a.x,z1a.x); zp[1]=fpair(z0a.y,z1a.y);
    zp[2]=fpair(z0a.z,z1a.z); zp[3]=fpair(z0a.w,z1a.w);
    zp[4]=fpair(z0b.x,z1b.x); zp[5]=fpair(z0b.y,z1b.y);
    zp[6]=fpair(z0b.z,z1b.z); zp[7]=fpair(z0b.w,z1b.w);
    up[0]=fpair(v0.x,v1.x);   up[1]=fpair(v0.y,v1.y);
    up[2]=fpair(v0.z,v1.z);   up[3]=fpair(v0.w,v1.w);

    const ulonglong2* M2 = (const ulonglong2*)&sM[i*256];
    const ulonglong2* K2 = (const ulonglong2*)&sK[i*128];
    const ulonglong2* N2 = (const ulonglong2*)&sN[i*64];
    ull acc[SDIM];
    // phase A: input contribution (frees zp/up before state matvec)
    #pragma unroll
    for (int s=0;s<SDIM;s++){
      ulonglong2 k0p = K2[s*4+0];
      ull a = fmul2(k0p.x, zp[0]);
      ffma2(a, k0p.y, zp[1]);
      ulonglong2 k1p = K2[s*4+1]; ffma2(a, k1p.x, zp[2]); ffma2(a, k1p.y, zp[3]);
      ulonglong2 k2p = K2[s*4+2]; ffma2(a, k2p.x, zp[4]); ffma2(a, k2p.y, zp[5]);
      ulonglong2 k3p = K2[s*4+3]; ffma2(a, k3p.x, zp[6]); ffma2(a, k3p.y, zp[7]);
      ulonglong2 n0p = N2[s*2+0]; ffma2(a, n0p.x, up[0]); ffma2(a, n0p.y, up[1]);
      ulonglong2 n1p = N2[s*2+1]; ffma2(a, n1p.x, up[2]); ffma2(a, n1p.y, up[3]);
      acc[s]=a;
    }
    // phase B: state matvec
    #pragma unroll
    for (int s=0;s<SDIM;s++){
      ull a = acc[s];
      #pragma unroll
      for (int jj=0;jj<8;jj++){
        ulonglong2 mm = M2[s*8+jj];
        ffma2(a, mm.x, xp[2*jj]);
        ffma2(a, mm.y, xp[2*jj+1]);
      }
      acc[s]=a;
    }
    #pragma unroll
    for (int s=0;s<SDIM;s++) xp[s]=acc[s];

    if (PHASE==3){
      float a0[SDIM], a1[SDIM];
      #pragma unroll
      for (int s=0;s<SDIM;s++) unpack2(xp[s], a0[s], a1[s]);
      float4* o0 = (float4*)(out + (((size_t)b0*T_SEQ) + (size_t)(k0+i))*SDIM);
      float4* o1 = (float4*)(out + (((size_t)(b0+1)*T_SEQ) + (size_t)(k0+i))*SDIM);
      o0[0]=make_float4(a0[0],a0[1],a0[2],a0[3]);
      o0[1]=make_float4(a0[4],a0[5],a0[6],a0[7]);
      o0[2]=make_float4(a0[8],a0[9],a0[10],a0[11]);
      o0[3]=make_float4(a0[12],a0[13],a0[14],a0[15]);
      o1[0]=make_float4(a1[0],a1[1],a1[2],a1[3]);
      o1[1]=make_float4(a1[4],a1[5],a1[6],a1[7]);
      o1[2]=make_float4(a1[8],a1[9],a1[10],a1[11]);
      o1[3]=make_float4(a1[12],a1[13],a1[14],a1[15]);
    }
  }
  if (PHASE==1){
    #pragma unroll
    for (int s=0;s<SDIM;s++)
      *(ull*)&g_d[((size_t)(c*SDIM+s))*BATCH + b0] = xp[s];
  }
}

// P2: exact serial combine across chunks, one thread per batch. Phi cached in smem.
__global__ void __launch_bounds__(TPB) pass2_kernel(const float* __restrict__ x0)
{
  __shared__ float sPhi[NPHI*256];
  for (int e=threadIdx.x; e<NPHI*256; e+=TPB) sPhi[e]=g_Phi[e];
  const int b = blockIdx.x*TPB + threadIdx.x;
  float x[16];
  #pragma unroll
  for(int s=0;s<16;s++) x[s]=x0[s];
  __syncthreads();
  #pragma unroll
  for(int s=0;s<16;s++) g_xs[(size_t)s*BATCH + b]=x[s];
  for (int c=1;c<CH;c++){
    int pidx = c-1; if (pidx > NPHI-1) pidx = NPHI-1;
    const float* Phi=&sPhi[pidx*256];
    float dd[16];
    #pragma unroll
    for(int s=0;s<16;s++) dd[s]=g_d[((size_t)((c-1)*16+s))*BATCH + b];
    float xn[16];
    #pragma unroll
    for(int s=0;s<16;s++){
      float a=dd[s];
      #pragma unroll
      for(int jj=0;jj<16;jj++) a+=Phi[s*16+jj]*x[jj];
      xn[s]=a;
    }
    #pragma unroll
    for(int s=0;s<16;s++) x[s]=xn[s];
    #pragma unroll
    for(int s=0;s<16;s++) g_xs[((size_t)(c*16+s))*BATCH + b]=x[s];
  }
}

extern "C" void kernel_launch(void* const* d_in, const int* in_sizes, int n_in,
                              void* d_out, int out_size)
{
  const float* obs = (const float*)d_in[0];
  const float* u   = (const float*)d_in[1];
  const float* A   = (const float*)d_in[2];
  const float* B   = (const float*)d_in[3];
  const float* C   = (const float*)d_in[4];
  const float* Q   = (const float*)d_in[5];
  const float* R   = (const float*)d_in[6];
  const float* x0  = (const float*)d_in[7];
  float* out = (float*)d_out;

  riccati_kernel<<<1, 256>>>(A, B, C, Q, R);

  dim3 grid1(BATCH/(TPB*NB), CH);
  pass_kernel<1><<<grid1, TPB>>>(obs, u, out);
  pass2_kernel<<<BATCH/TPB, TPB>>>(x0);
  pass_kernel<3><<<grid1, TPB>>>(obs, u, out);
}

// round 5
// speedup vs baseline: 1.5742x; 1.1397x over previous
#include <cuda_runtime.h>
#include <cstdint>
#include <cstddef>

#define BATCH 4096
#define T_SEQ 512
#define SDIM  16
#define ODIM  8
#define IDIM  4
#define RS    16
#define CH    32
#define LCH   16
#define NB    2
#define TPB   128

typedef unsigned long long ull;

__device__ float g_M [RS*256];
__device__ float g_Kg[RS*128];
__device__ float g_Ng[RS*64];
__device__ float g_Phi[2*256];
__device__ float g_W  [2*16*192];               // [type][s][j*12 + c]  (c: 0..7 z, 8..11 u)
__device__ float g_d [(size_t)CH*SDIM*BATCH];   // [c][s][b]
__device__ float g_xs[(size_t)CH*SDIM*BATCH];   // [c][s][b]

// ---------- f32x2 helpers ----------
__device__ __forceinline__ ull fpair(float a, float b){
  ull r; asm("mov.b64 %0, {%1,%2};" : "=l"(r) : "f"(a), "f"(b)); return r;
}
__device__ __forceinline__ ull fdup(float a){ return fpair(a,a); }
__device__ __forceinline__ void unpack2(ull p, float& a, float& b){
  asm("mov.b64 {%0,%1}, %2;" : "=f"(a), "=f"(b) : "l"(p));
}
__device__ __forceinline__ void ffma2(ull& d, ull a, ull b){
  asm("fma.rn.f32x2 %0, %1, %2, %0;" : "+l"(d) : "l"(a), "l"(b));
}

// ---------- fully unrolled 4x4 inverse ----------
__device__ __forceinline__ void inv4x4(const float* m, int ld, float* inv){
  float a00=m[0],      a01=m[1],      a02=m[2],      a03=m[3];
  float a10=m[ld],     a11=m[ld+1],   a12=m[ld+2],   a13=m[ld+3];
  float a20=m[2*ld],   a21=m[2*ld+1], a22=m[2*ld+2], a23=m[2*ld+3];
  float a30=m[3*ld],   a31=m[3*ld+1], a32=m[3*ld+2], a33=m[3*ld+3];
  float s0=a00*a11-a01*a10, s1=a00*a12-a02*a10, s2=a00*a13-a03*a10;
  float s3=a01*a12-a02*a11, s4=a01*a13-a03*a11, s5=a02*a13-a03*a12;
  float c5=a22*a33-a23*a32, c4=a21*a33-a23*a31, c3=a21*a32-a22*a31;
  float c2=a20*a33-a23*a30, c1=a20*a32-a22*a30, c0=a20*a31-a21*a30;
  float det=s0*c5-s1*c4+s2*c3+s3*c2-s4*c1+s5*c0;
  float id=1.f/det;
  inv[0] =( a11*c5-a12*c4+a13*c3)*id;
  inv[1] =(-a01*c5+a02*c4-a03*c3)*id;
  inv[2] =( a31*s5-a32*s4+a33*s3)*id;
  inv[3] =(-a21*s5+a22*s4-a23*s3)*id;
  inv[4] =(-a10*c5+a12*c2-a13*c1)*id;
  inv[5] =( a00*c5-a02*c2+a03*c1)*id;
  inv[6] =(-a30*s5+a32*s2-a33*s1)*id;
  inv[7] =( a20*s5-a22*s2+a23*s1)*id;
  inv[8] =( a10*c4-a11*c2+a13*c0)*id;
  inv[9] =(-a00*c4+a01*c2-a03*c0)*id;
  inv[10]=( a30*s4-a31*s2+a33*s0)*id;
  inv[11]=(-a20*s4+a21*s2-a23*s0)*id;
  inv[12]=(-a10*c3+a11*c1-a12*c0)*id;
  inv[13]=( a00*c3-a01*c1+a02*c0)*id;
  inv[14]=(-a30*s3+a31*s1-a32*s0)*id;
  inv[15]=( a20*s3-a21*s1+a22*s0)*id;
}

// K1: Riccati + W/Phi composition. 1 block, 256 threads.
__global__ void riccati_kernel(const float* __restrict__ A_, const float* __restrict__ B_,
                               const float* __restrict__ C_, const float* __restrict__ Q_,
                               const float* __restrict__ R_)
{
  __shared__ float sA[256], sQ[256], sC[128], sB[64], sR[64], sCA[128], sCB[32];
  __shared__ float P[256], Tm[256], Pp[256], CP[128], S8[64], Sinv[64], KK[128];
  __shared__ float BufA[256], BufB[256];
  const int t = threadIdx.x;
  const int s = t>>4, j = t&15;

  sA[t]=A_[t]; sQ[t]=Q_[t];
  P[t] = (s==j)?1.f:0.f;
  if (t<128) sC[t]=C_[t];
  if (t<64){ sB[t]=B_[t]; sR[t]=R_[t]; }
  __syncthreads();
  if (t<128){ int o=t>>4, jj=t&15; float a=0.f;
    #pragma unroll
    for(int m=0;m<16;m++) a+=sC[o*16+m]*sA[m*16+jj];
    sCA[t]=a; }
  if (t<32){ int o=t>>2, ii=t&3; float a=0.f;
    #pragma unroll
    for(int m=0;m<16;m++) a+=sC[o*16+m]*sB[m*4+ii];
    sCB[t]=a; }
  __syncthreads();

  for (int k=0;k<RS;k++){
    { float a=0.f;                                    // Tm = A @ P
      #pragma unroll
      for(int m=0;m<16;m++) a+=sA[s*16+m]*P[m*16+j];
      Tm[t]=a; }
    __syncthreads();
    { float a=sQ[t];                                  // Pp = Tm A^T + Q
      #pragma unroll
      for(int m=0;m<16;m++) a+=Tm[s*16+m]*sA[j*16+m];
      Pp[t]=a; }
    __syncthreads();
    if (t<128){ int o=t>>4, jj=t&15; float a=0.f;     // CP = C @ Pp
      #pragma unroll
      for(int m=0;m<16;m++) a+=sC[o*16+m]*Pp[m*16+jj];
      CP[t]=a; }
    __syncthreads();
    if (t<64){ int o=t>>3, p=t&7; float a=sR[t];      // S = CP C^T + R
      #pragma unroll
      for(int m=0;m<16;m++) a+=CP[o*16+m]*sC[p*16+m];
      S8[t]=a; }
    __syncthreads();
    if (t==0){                                        // 8x8 SPD inverse via Schur
      float Ai[16]; inv4x4(&S8[0], 8, Ai);
      float W[16];
      #pragma unroll
      for(int i4=0;i4<4;i4++)
        #pragma unroll
        for(int j4=0;j4<4;j4++){ float a=0.f;
          #pragma unroll
          for(int m=0;m<4;m++) a+=S8[(4+i4)*8+m]*Ai[m*4+j4];
          W[i4*4+j4]=a; }
      float Sc[16];
      #pragma unroll
      for(int i4=0;i4<4;i4++)
        #pragma unroll
        for(int j4=0;j4<4;j4++){ float a=S8[(4+i4)*8+4+j4];
          #pragma unroll
          for(int m=0;m<4;m++) a-=W[i4*4+m]*S8[m*8+4+j4];
          Sc[i4*4+j4]=a; }
      float Sci[16]; inv4x4(Sc, 4, Sci);
      float X21[16];
      #pragma unroll
      for(int i4=0;i4<4;i4++)
        #pragma unroll
        for(int j4=0;j4<4;j4++){ float a=0.f;
          #pragma unroll
          for(int m=0;m<4;m++) a+=Sci[i4*4+m]*W[m*4+j4];
          X21[i4*4+j4]=-a; }
      float X11[16];
      #pragma unroll
      for(int i4=0;i4<4;i4++)
        #pragma unroll
        for(int j4=0;j4<4;j4++){ float a=Ai[i4*4+j4];
          #pragma unroll
          for(int m=0;m<4;m++) a-=W[m*4+i4]*X21[m*4+j4];
          X11[i4*4+j4]=a; }
      #pragma unroll
      for(int o=0;o<8;o++)
        #pragma unroll
        for(int p=0;p<8;p++){
          float v;
          if (o<4 && p<4) v=X11[o*4+p];
          else if (o<4)   v=X21[(p-4)*4+o];
          else if (p<4)   v=X21[(o-4)*4+p];
          else            v=Sci[(o-4)*4+(p-4)];
          Sinv[o*8+p]=v; }
    }
    __syncthreads();
    if (t<128){ int ss=t>>3, o=t&7; float a=0.f;      // K = CP^T Sinv
      #pragma unroll
      for(int p=0;p<8;p++) a+=CP[p*16+ss]*Sinv[p*8+o];
      KK[t]=a; }
    __syncthreads();
    { float a=Pp[t], mg=sA[t];                        // P_post, M_k
      #pragma unroll
      for(int o=0;o<8;o++){ float kv=KK[s*8+o]; a-=kv*CP[o*16+j]; mg-=kv*sCA[o*16+j]; }
      P[t]=a;
      g_M[k*256+t]=mg; }
    if (t<128) g_Kg[k*128+t]=KK[t];
    if (t<64){ int ss=t>>2, ii=t&3; float a=sB[t];    // N_k
      #pragma unroll
      for(int o=0;o<8;o++) a-=KK[ss*8+o]*sCB[o*4+ii];
      g_Ng[k*64+t]=a; }
    __syncthreads();
  }

  // W + Phi per chunk type: suffix products S_j = M_last..M_{j+1}; Wz_j=S_j K_j, Wu_j=S_j N_j
  for (int tt=0; tt<2; tt++){
    float* Sb = BufA; float* Sn = BufB;
    Sb[t] = (s==j)?1.f:0.f;
    __syncthreads();
    for (int jj=LCH-1; jj>=0; jj--){
      const int k = (tt==0)? jj : (RS-1);
      if (t<128){ int ss=t>>3, o=t&7; float a=0.f;    // Wz
        #pragma unroll
        for(int m=0;m<16;m++) a+=Sb[ss*16+m]*g_Kg[k*128+m*8+o];
        g_W[(tt*16+ss)*192 + jj*12 + o] = a; }
      else { int e=t-128; int ss=e>>2, ii=e&3;        // Wu (threads 128..191)
        if (e<64){ float a=0.f;
          #pragma unroll
          for(int m=0;m<16;m++) a+=Sb[ss*16+m]*g_Ng[k*64+m*4+ii];
          g_W[(tt*16+ss)*192 + jj*12 + 8 + ii] = a; } }
      { float a=0.f;                                  // S = S @ M_jj
        #pragma unroll
        for(int m=0;m<16;m++) a+=Sb[s*16+m]*g_M[k*256+m*16+j];
        Sn[t]=a; }
      __syncthreads();
      float* tmp=Sb; Sb=Sn; Sn=tmp;
    }
    g_Phi[tt*256+t]=Sb[t];
    __syncthreads();
  }
}

// P1: chunk response from zero state — d[c][:][b] = W(type) @ inputs(chunk c, batch b)
__global__ void __launch_bounds__(TPB) resp_kernel(const float* __restrict__ obs,
                                                   const float* __restrict__ u)
{
  __shared__ ull sW[16*192];                          // duplicated pairs, 24KB
  const int c  = blockIdx.y;
  const int tt = (c==0)?0:1;
  for (int idx=threadIdx.x; idx<16*192; idx+=TPB)
    sW[idx] = fdup(g_W[tt*16*192 + idx]);
  const int b0 = (blockIdx.x*TPB + threadIdx.x)*NB;
  const int k0 = c*LCH;
  ull acc[SDIM];
  #pragma unroll
  for (int s=0;s<SDIM;s++) acc[s]=0ull;
  __syncthreads();

  const float* ob0 = obs + ((size_t)b0*T_SEQ + k0)*ODIM;
  const float* ob1 = ob0 + (size_t)T_SEQ*ODIM;
  const float* uu0 = u   + ((size_t)b0*T_SEQ + k0)*IDIM;
  const float* uu1 = uu0 + (size_t)T_SEQ*IDIM;

  for (int jj=0;jj<LCH;jj++){
    float4 z0a = *(const float4*)(ob0 + jj*ODIM);
    float4 z0b = *(const float4*)(ob0 + jj*ODIM + 4);
    float4 z1a = *(const float4*)(ob1 + jj*ODIM);
    float4 z1b = *(const float4*)(ob1 + jj*ODIM + 4);
    float4 v0  = *(const float4*)(uu0 + jj*IDIM);
    float4 v1  = *(const float4*)(uu1 + jj*IDIM);
    ull ip[12];
    ip[0]=fpair(z0a.x,z1a.x); ip[1]=fpair(z0a.y,z1a.y);
    ip[2]=fpair(z0a.z,z1a.z); ip[3]=fpair(z0a.w,z1a.w);
    ip[4]=fpair(z0b.x,z1b.x); ip[5]=fpair(z0b.y,z1b.y);
    ip[6]=fpair(z0b.z,z1b.z); ip[7]=fpair(z0b.w,z1b.w);
    ip[8]=fpair(v0.x,v1.x);   ip[9]=fpair(v0.y,v1.y);
    ip[10]=fpair(v0.z,v1.z);  ip[11]=fpair(v0.w,v1.w);
    #pragma unroll
    for (int s=0;s<SDIM;s++){
      const ulonglong2* Wr = (const ulonglong2*)&sW[s*192 + jj*12];
      ull a = acc[s];
      #pragma unroll
      for (int q=0;q<6;q++){
        ulonglong2 w = Wr[q];
        ffma2(a, w.x, ip[2*q]);
        ffma2(a, w.y, ip[2*q+1]);
      }
      acc[s]=a;
    }
  }
  #pragma unroll
  for (int s=0;s<SDIM;s++)
    *(ull*)&g_d[((size_t)(c*SDIM+s))*BATCH + b0] = acc[s];
}

// P2: exact serial combine across chunks, one thread per batch.
__global__ void __launch_bounds__(TPB) pass2_kernel(const float* __restrict__ x0)
{
  __shared__ float sPhi[2*256];
  for (int e=threadIdx.x; e<2*256; e+=TPB) sPhi[e]=g_Phi[e];
  const int b = blockIdx.x*TPB + threadIdx.x;
  float x[16];
  #pragma unroll
  for(int s=0;s<16;s++) x[s]=x0[s];
  __syncthreads();
  #pragma unroll
  for(int s=0;s<16;s++) g_xs[(size_t)s*BATCH + b]=x[s];
  for (int c=1;c<CH;c++){
    const float* Phi=&sPhi[((c-1)==0?0:1)*256];
    float dd[16];
    #pragma unroll
    for(int s=0;s<16;s++) dd[s]=g_d[((size_t)((c-1)*16+s))*BATCH + b];
    float xn[16];
    #pragma unroll
    for(int s=0;s<16;s++){
      float a=dd[s];
      #pragma unroll
      for(int jj=0;jj<16;jj++) a+=Phi[s*16+jj]*x[jj];
      xn[s]=a;
    }
    #pragma unroll
    for(int s=0;s<16;s++) x[s]=xn[s];
    #pragma unroll
    for(int s=0;s<16;s++) g_xs[((size_t)(c*16+s))*BATCH + b]=x[s];
  }
}

// P3: serial recurrence within chunk from true start state; writes all outputs.
__global__ void __launch_bounds__(TPB, 4) pass3_kernel(const float* __restrict__ obs,
                                                       const float* __restrict__ u,
                                                       float* __restrict__ out)
{
  extern __shared__ ull dsm[];                        // [sM 16*256 | sK 16*128 | sN 16*64]
  ull* sM = dsm;
  ull* sK = dsm + 16*256;
  ull* sN = dsm + 16*256 + 16*128;
  const int c  = blockIdx.y;
  const bool trans = (c==0);
  const int nset = trans ? 16 : 1;
  for (int idx=threadIdx.x; idx<nset*256; idx+=TPB){
    int i=idx>>8, e=idx&255; int kk = trans ? i : (RS-1);
    sM[idx]=fdup(g_M[kk*256+e]);
  }
  for (int idx=threadIdx.x; idx<nset*128; idx+=TPB){
    int i=idx>>7, e=idx&127; int kk = trans ? i : (RS-1);
    sK[idx]=fdup(g_Kg[kk*128+e]);
  }
  for (int idx=threadIdx.x; idx<nset*64; idx+=TPB){
    int i=idx>>6, e=idx&63; int kk = trans ? i : (RS-1);
    sN[idx]=fdup(g_Ng[kk*64+e]);
  }
  const int b0 = (blockIdx.x*TPB + threadIdx.x)*NB;
  const int k0 = c*LCH;
  ull xp[SDIM];
  #pragma unroll
  for (int s=0;s<SDIM;s++)
    xp[s] = *(const ull*)&g_xs[((size_t)(c*SDIM+s))*BATCH + b0];
  __syncthreads();

  const float* ob0 = obs + ((size_t)b0*T_SEQ + k0)*ODIM;
  const float* ob1 = ob0 + (size_t)T_SEQ*ODIM;
  const float* uu0 = u   + ((size_t)b0*T_SEQ + k0)*IDIM;
  const float* uu1 = uu0 + (size_t)T_SEQ*IDIM;

  for (int i=0;i<LCH;i++){
    const int mi = trans ? i : 0;
    float4 z0a = *(const float4*)(ob0 + i*ODIM);
    float4 z0b = *(const float4*)(ob0 + i*ODIM + 4);
    float4 z1a = *(const float4*)(ob1 + i*ODIM);
    float4 z1b = *(const float4*)(ob1 + i*ODIM + 4);
    float4 v0  = *(const float4*)(uu0 + i*IDIM);
    float4 v1  = *(const float4*)(uu1 + i*IDIM);
    ull zp[8], up[4];
    zp[0]=fpair(z0a.x,z1a.x); zp[1]=fpair(z0a.y,z1a.y);
    zp[2]=fpair(z0a.z,z1a.z); zp[3]=fpair(z0a.w,z1a.w);
    zp[4]=fpair(z0b.x,z1b.x); zp[5]=fpair(z0b.y,z1b.y);
    zp[6]=fpair(z0b.z,z1b.z); zp[7]=fpair(z0b.w,z1b.w);
    up[0]=fpair(v0.x,v1.x);   up[1]=fpair(v0.y,v1.y);
    up[2]=fpair(v0.z,v1.z);   up[3]=fpair(v0.w,v1.w);

    const ulonglong2* M2 = (const ulonglong2*)&sM[mi*256];
    const ulonglong2* K2 = (const ulonglong2*)&sK[mi*128];
    const ulonglong2* N2 = (const ulonglong2*)&sN[mi*64];
    ull acc[SDIM];
    #pragma unroll
    for (int s=0;s<SDIM;s++){
      ulonglong2 k0p = K2[s*4+0];
      ull a = 0ull;
      ffma2(a, k0p.x, zp[0]); ffma2(a, k0p.y, zp[1]);
      ulonglong2 k1p = K2[s*4+1]; ffma2(a, k1p.x, zp[2]); ffma2(a, k1p.y, zp[3]);
      ulonglong2 k2p = K2[s*4+2]; ffma2(a, k2p.x, zp[4]); ffma2(a, k2p.y, zp[5]);
      ulonglong2 k3p = K2[s*4+3]; ffma2(a, k3p.x, zp[6]); ffma2(a, k3p.y, zp[7]);
      ulonglong2 n0p = N2[s*2+0]; ffma2(a, n0p.x, up[0]); ffma2(a, n0p.y, up[1]);
      ulonglong2 n1p = N2[s*2+1]; ffma2(a, n1p.x, up[2]); ffma2(a, n1p.y, up[3]);
      acc[s]=a;
    }
    #pragma unroll
    for (int s=0;s<SDIM;s++){
      ull a = acc[s];
      #pragma unroll
      for (int jj=0;jj<8;jj++){
        ulonglong2 mm = M2[s*8+jj];
        ffma2(a, mm.x, xp[2*jj]);
        ffma2(a, mm.y, xp[2*jj+1]);
      }
      acc[s]=a;
    }
    #pragma unroll
    for (int s=0;s<SDIM;s++) xp[s]=acc[s];

    {
      float a0[SDIM], a1[SDIM];
      #pragma unroll
      for (int s=0;s<SDIM;s++) unpack2(xp[s], a0[s], a1[s]);
      float4* o0 = (float4*)(out + (((size_t)b0*T_SEQ) + (size_t)(k0+i))*SDIM);
      float4* o1 = (float4*)(out + (((size_t)(b0+1)*T_SEQ) + (size_t)(k0+i))*SDIM);
      o0[0]=make_float4(a0[0],a0[1],a0[2],a0[3]);
      o0[1]=make_float4(a0[4],a0[5],a0[6],a0[7]);
      o0[2]=make_float4(a0[8],a0[9],a0[10],a0[11]);
      o0[3]=make_float4(a0[12],a0[13],a0[14],a0[15]);
      o1[0]=make_float4(a1[0],a1[1],a1[2],a1[3]);
      o1[1]=make_float4(a1[4],a1[5],a1[6],a1[7]);
      o1[2]=make_float4(a1[8],a1[9],a1[10],a1[11]);
      o1[3]=make_float4(a1[12],a1[13],a1[14],a1[15]);
    }
  }
}

extern "C" void kernel_launch(void* const* d_in, const int* in_sizes, int n_in,
                              void* d_out, int out_size)
{
  const float* obs = (const float*)d_in[0];
  const float* u   = (const float*)d_in[1];
  const float* A   = (const float*)d_in[2];
  const float* B   = (const float*)d_in[3];
  const float* C   = (const float*)d_in[4];
  const float* Q   = (const float*)d_in[5];
  const float* R   = (const float*)d_in[6];
  const float* x0  = (const float*)d_in[7];
  float* out = (float*)d_out;

  const int dynsmem = (16*256 + 16*128 + 16*64) * (int)sizeof(ull); // 57344
  cudaFuncSetAttribute(pass3_kernel, cudaFuncAttributeMaxDynamicSharedMemorySize, dynsmem);

  riccati_kernel<<<1, 256>>>(A, B, C, Q, R);

  dim3 grid1(BATCH/(TPB*NB), CH);
  resp_kernel<<<grid1, TPB>>>(obs, u);
  pass2_kernel<<<BATCH/TPB, TPB>>>(x0);
  pass3_kernel<<<grid1, TPB, dynsmem>>>(obs, u, out);
}